// round 3
// baseline (speedup 1.0000x reference)
#include <cuda_runtime.h>
#include <cstdint>

// ---------------- scratch (device globals; no allocation allowed) ----------------
__device__ float g_s1[1024 * 36 * 32 * 32];   // conv1 out (pooled)
__device__ float g_s2[1024 * 36 * 16 * 16];   // conv2 out (pooled)
__device__ float g_s3[1024 * 36 * 8 * 8];     // conv3 out (pooled)
__device__ float g_p1[1024 * 12 * 32 * 32];   // private conv out (pooled)
__device__ float g_x24[1024 * 24];            // concat [h | p]
__device__ float g_U[16 * 36 * 36];           // Winograd-transformed hidden weights U[k][ci][oc]

// ---------------- Winograd weight transform: U = G g G^T ----------------
// g: [36 oc][36 ci][3][3]  ->  U[k][ci][oc], k = 4*r + c
__global__ void wino_wt_kernel(const float* __restrict__ g, float* __restrict__ U)
{
    int idx = blockIdx.x * blockDim.x + threadIdx.x;
    if (idx >= 36 * 36) return;
    int oc = idx / 36, ci = idx % 36;
    const float* gp = g + (size_t)(oc * 36 + ci) * 9;
    float a[3][3];
    #pragma unroll
    for (int r = 0; r < 3; r++)
        #pragma unroll
        for (int c = 0; c < 3; c++) a[r][c] = gp[r * 3 + c];
    float T[4][3];
    #pragma unroll
    for (int c = 0; c < 3; c++) {
        T[0][c] = a[0][c];
        T[1][c] = 0.5f * (a[0][c] + a[1][c] + a[2][c]);
        T[2][c] = 0.5f * (a[0][c] - a[1][c] + a[2][c]);
        T[3][c] = a[2][c];
    }
    #pragma unroll
    for (int r = 0; r < 4; r++) {
        float t0 = T[r][0], t1 = T[r][1], t2 = T[r][2];
        float u0 = t0;
        float u1 = 0.5f * (t0 + t1 + t2);
        float u2 = 0.5f * (t0 - t1 + t2);
        float u3 = t2;
        U[((r * 4 + 0) * 36 + ci) * 36 + oc] = u0;
        U[((r * 4 + 1) * 36 + ci) * 36 + oc] = u1;
        U[((r * 4 + 2) * 36 + ci) * 36 + oc] = u2;
        U[((r * 4 + 3) * 36 + ci) * 36 + oc] = u3;
    }
}

// ---------------- Winograd F(2x2,3x3) conv 36->36 + relu + maxpool2 ----------------
// Block = (strip, image). Strip = TROWS x (S/2) Winograd tiles = 32 tiles.
// Each 2x2 Winograd output tile IS one maxpool window -> fused epilogue.
template <int S, int TROWS>
__global__ void __launch_bounds__(288, 2)
wino_conv_kernel(const float* __restrict__ x, const float* __restrict__ U,
                 const float* __restrict__ Bv, float* __restrict__ out)
{
    constexpr int IC = 36, OC = 36;
    constexpr int TC = S / 2;          // tile cols
    constexpr int P  = S + 4;          // padded col stride
    constexpr int SR = 2 * TROWS + 2;  // staged input rows (with halo)
    constexpr int NT = 288;
    static_assert(TROWS * TC == 32, "strip must be 32 tiles");
    extern __shared__ float smem[];
    float* sx = smem;                   // IC * SR * P
    float* sV = smem + IC * SR * P;     // 16 * IC * 32

    const int strip = blockIdx.x;
    const int b     = blockIdx.y;
    const int tid   = threadIdx.x;

    for (int i = tid; i < IC * SR * P; i += NT) sx[i] = 0.f;
    __syncthreads();

    const int rbase = strip * 2 * TROWS - 1;
    const int gr0   = rbase < 0 ? 0 : rbase;
    const int gr1   = (rbase + SR > S) ? S : rbase + SR;
    const int nrow  = gr1 - gr0;
    const float* xb = x + (size_t)b * IC * S * S;
    for (int i = tid; i < IC * nrow * S; i += NT) {
        int c  = i / (nrow * S);
        int rr = (i / S) % nrow;
        int cc = i % S;
        int gr = gr0 + rr;
        sx[c * SR * P + (gr - rbase) * P + cc + 1] = xb[c * S * S + gr * S + cc];
    }
    __syncthreads();

    // ---- Phase A: input transform V = B^T d B, into sV[k][ci][tile] ----
    for (int it = tid; it < IC * 32; it += NT) {
        int ci = it >> 5, tile = it & 31;
        int tr = tile / TC, tc = tile % TC;
        const float* base = sx + ci * SR * P + 2 * tr * P + 2 * tc;
        float d[4][4];
        #pragma unroll
        for (int r = 0; r < 4; r++)
            #pragma unroll
            for (int c = 0; c < 4; c++) d[r][c] = base[r * P + c];
        float w[4][4];
        #pragma unroll
        for (int c = 0; c < 4; c++) {
            w[0][c] = d[0][c] - d[2][c];
            w[1][c] = d[1][c] + d[2][c];
            w[2][c] = d[2][c] - d[1][c];
            w[3][c] = d[1][c] - d[3][c];
        }
        #pragma unroll
        for (int r = 0; r < 4; r++) {
            float v0 = w[r][0] - w[r][2];
            float v1 = w[r][1] + w[r][2];
            float v2 = w[r][2] - w[r][1];
            float v3 = w[r][1] - w[r][3];
            sV[((r * 4 + 0) * IC + ci) * 32 + tile] = v0;
            sV[((r * 4 + 1) * IC + ci) * 32 + tile] = v1;
            sV[((r * 4 + 2) * IC + ci) * 32 + tile] = v2;
            sV[((r * 4 + 3) * IC + ci) * 32 + tile] = v3;
        }
    }
    __syncthreads();

    // ---- Phase B: 16 element-wise GEMMs. thread = (oc group of 4, tile). ----
    const int o4   = tid >> 5;   // 0..8
    const int tile = tid & 31;
    float4 acc[16];
    #pragma unroll
    for (int k = 0; k < 16; k++) acc[k] = make_float4(0.f, 0.f, 0.f, 0.f);
    const float4* U4 = reinterpret_cast<const float4*>(U);
    for (int ci = 0; ci < IC; ci++) {
        #pragma unroll
        for (int k = 0; k < 16; k++) {
            float  v = sV[(k * IC + ci) * 32 + tile];
            float4 u = __ldg(U4 + (k * IC + ci) * 9 + o4);   // warp-uniform -> broadcast
            acc[k].x = fmaf(v, u.x, acc[k].x);
            acc[k].y = fmaf(v, u.y, acc[k].y);
            acc[k].z = fmaf(v, u.z, acc[k].z);
            acc[k].w = fmaf(v, u.w, acc[k].w);
        }
    }

    // ---- Output transform + fused maxpool + bias + relu ----
    const int tr = tile / TC, tc = tile % TC;
    constexpr int Sp = S / 2;
    const int prow = strip * TROWS + tr;
    #pragma unroll
    for (int j = 0; j < 4; j++) {
        int oc = 4 * o4 + j;
        float m[16];
        #pragma unroll
        for (int k = 0; k < 16; k++)
            m[k] = (j == 0) ? acc[k].x : (j == 1) ? acc[k].y : (j == 2) ? acc[k].z : acc[k].w;
        float t0[4], t1[4];
        #pragma unroll
        for (int c = 0; c < 4; c++) {
            t0[c] = m[0 * 4 + c] + m[1 * 4 + c] + m[2 * 4 + c];
            t1[c] = m[1 * 4 + c] - m[2 * 4 + c] - m[3 * 4 + c];
        }
        float y00 = t0[0] + t0[1] + t0[2];
        float y01 = t0[1] - t0[2] - t0[3];
        float y10 = t1[0] + t1[1] + t1[2];
        float y11 = t1[1] - t1[2] - t1[3];
        float mx = fmaxf(fmaxf(y00, y01), fmaxf(y10, y11)) + __ldg(Bv + oc);
        out[(((size_t)b * OC + oc) * Sp + prow) * Sp + tc] = fmaxf(mx, 0.f);
    }
}

// ---------------- direct conv3x3 + act + maxpool2 (R1, known-good) ----------------
template <int IC, int OC, int S, bool LEAKY, bool USE_DOM>
__global__ void convpool_kernel(const float* __restrict__ x,
                                const float* __restrict__ Wbase,
                                const float* __restrict__ Bbase,
                                const int* __restrict__ dom_ptr,
                                float* __restrict__ out)
{
    constexpr int PH = S + 2;
    constexpr int P  = S + 4;
    constexpr int HT = S / 4;
    constexpr int Sp = S / 2;
    extern __shared__ float smem[];
    float* sx = smem;                       // IC * PH * P
    float* sw = smem + IC * PH * P;         // OC * IC * 9

    const int b   = blockIdx.x;
    const int tid = threadIdx.x;
    const int nt  = blockDim.x;

    int dom = 0;
    if (USE_DOM) dom = dom_ptr[0];
    const float* W  = Wbase + (size_t)dom * OC * IC * 9;
    const float* Bv = Bbase + (size_t)dom * OC;

    for (int i = tid; i < IC * PH * P; i += nt) sx[i] = 0.f;
    __syncthreads();
    const float* xb = x + (size_t)b * IC * S * S;
    for (int i = tid; i < IC * S * S; i += nt) {
        int c  = i / (S * S);
        int r  = (i / S) % S;
        int cc = i % S;
        sx[c * PH * P + (r + 1) * P + (cc + 1)] = xb[i];
    }
    for (int i = tid; i < OC * IC * 9; i += nt) sw[i] = W[i];
    __syncthreads();

    constexpr int tilesPerOc = HT * HT;
    constexpr int tiles = OC * tilesPerOc;
    for (int t = tid; t < tiles; t += nt) {
        int oc  = t / tilesPerOc;
        int rem = t - oc * tilesPerOc;
        int ty  = rem / HT;
        int tx  = rem - ty * HT;

        float acc[16];
        #pragma unroll
        for (int i = 0; i < 16; i++) acc[i] = 0.f;

        const float* wp    = sw + oc * IC * 9;
        const float* xbase = sx + (4 * ty) * P + 4 * tx;

        for (int ci = 0; ci < IC; ci++) {
            const float* xp = xbase + ci * PH * P;
            float w0 = wp[0], w1 = wp[1], w2 = wp[2],
                  w3 = wp[3], w4 = wp[4], w5 = wp[5],
                  w6 = wp[6], w7 = wp[7], w8 = wp[8];
            wp += 9;
            float p[6][6];
            #pragma unroll
            for (int r = 0; r < 6; r++) {
                float4 a  = *reinterpret_cast<const float4*>(xp + r * P);
                float4 bq = *reinterpret_cast<const float4*>(xp + r * P + 4);
                p[r][0] = a.x;  p[r][1] = a.y;  p[r][2] = a.z;  p[r][3] = a.w;
                p[r][4] = bq.x; p[r][5] = bq.y;
            }
            #pragma unroll
            for (int r = 0; r < 4; r++) {
                #pragma unroll
                for (int c = 0; c < 4; c++) {
                    float s = acc[r * 4 + c];
                    s = fmaf(w0, p[r][c],         s);
                    s = fmaf(w1, p[r][c + 1],     s);
                    s = fmaf(w2, p[r][c + 2],     s);
                    s = fmaf(w3, p[r + 1][c],     s);
                    s = fmaf(w4, p[r + 1][c + 1], s);
                    s = fmaf(w5, p[r + 1][c + 2], s);
                    s = fmaf(w6, p[r + 2][c],     s);
                    s = fmaf(w7, p[r + 2][c + 1], s);
                    s = fmaf(w8, p[r + 2][c + 2], s);
                    acc[r * 4 + c] = s;
                }
            }
        }
        float bias = Bv[oc];
        float* ob = out + (((size_t)b * OC + oc) * Sp + 2 * ty) * Sp + 2 * tx;
        #pragma unroll
        for (int pr = 0; pr < 2; pr++) {
            #pragma unroll
            for (int pc = 0; pc < 2; pc++) {
                float m = fmaxf(fmaxf(acc[(2*pr)*4 + 2*pc],   acc[(2*pr)*4 + 2*pc + 1]),
                                fmaxf(acc[(2*pr+1)*4 + 2*pc], acc[(2*pr+1)*4 + 2*pc + 1]));
                m += bias;
                float v;
                if (LEAKY) v = (m > 0.f) ? m : 0.001f * m;
                else       v = fmaxf(m, 0.f);
                ob[pr * Sp + pc] = v;
            }
        }
    }
}

// ---------------- FC: [B,K] @ W[12,K]^T + b -> concat buffer ----------------
template <int K, bool RELU, bool USE_DOM>
__global__ void fc12_kernel(const float* __restrict__ x,
                            const float* __restrict__ Wbase,
                            const float* __restrict__ Bbase,
                            const int* __restrict__ dom_ptr,
                            float* __restrict__ out, int out_off)
{
    const int warp = threadIdx.x >> 5;
    const int lane = threadIdx.x & 31;
    const int b = blockIdx.x * 8 + warp;
    int dom = 0;
    if (USE_DOM) dom = dom_ptr[0];
    const float* W = Wbase + (size_t)dom * 12 * K;
    const float4* xr = reinterpret_cast<const float4*>(x + (size_t)b * K);

    float4 acc[12];
    #pragma unroll
    for (int j = 0; j < 12; j++) acc[j] = make_float4(0.f, 0.f, 0.f, 0.f);

    for (int k4 = lane; k4 < K / 4; k4 += 32) {
        float4 xv = xr[k4];
        #pragma unroll
        for (int j = 0; j < 12; j++) {
            float4 wv = reinterpret_cast<const float4*>(W + (size_t)j * K)[k4];
            acc[j].x = fmaf(xv.x, wv.x, acc[j].x);
            acc[j].y = fmaf(xv.y, wv.y, acc[j].y);
            acc[j].z = fmaf(xv.z, wv.z, acc[j].z);
            acc[j].w = fmaf(xv.w, wv.w, acc[j].w);
        }
    }
    const float* Bv = Bbase + dom * 12;
    #pragma unroll
    for (int j = 0; j < 12; j++) {
        float s = (acc[j].x + acc[j].y) + (acc[j].z + acc[j].w);
        #pragma unroll
        for (int o = 16; o > 0; o >>= 1) s += __shfl_xor_sync(0xffffffffu, s, o);
        if (lane == j) {
            float v = s + Bv[j];
            if (RELU) v = fmaxf(v, 0.f);
            out[b * 24 + out_off + j] = v;
        }
    }
}

// ---------------- per-sample routed heads: 24 -> 28 -> 14 -> 5 ----------------
__global__ void heads_kernel(const float* __restrict__ x24,
                             const int* __restrict__ tt,
                             const float* __restrict__ W1, const float* __restrict__ b1,
                             const float* __restrict__ W2, const float* __restrict__ b2,
                             const float* __restrict__ W3, const float* __restrict__ b3,
                             float* __restrict__ out)
{
    const int warp = threadIdx.x >> 5;
    const int lane = threadIdx.x & 31;
    const int b = blockIdx.x * 8 + warp;
    const int t = tt[b];

    float xv = (lane < 24) ? x24[b * 24 + lane] : 0.f;

    const float* w1 = W1 + t * 28 * 24 + min(lane, 27) * 24;
    float h1 = 0.f;
    #pragma unroll
    for (int k = 0; k < 24; k++)
        h1 = fmaf(w1[k], __shfl_sync(0xffffffffu, xv, k), h1);
    if (lane < 28) h1 += b1[t * 28 + lane];
    h1 = fmaxf(h1, 0.f);
    if (lane >= 28) h1 = 0.f;

    const float* w2 = W2 + t * 14 * 28 + min(lane, 13) * 28;
    float h2 = 0.f;
    #pragma unroll
    for (int k = 0; k < 28; k++)
        h2 = fmaf(w2[k], __shfl_sync(0xffffffffu, h1, k), h2);
    if (lane < 14) h2 += b2[t * 14 + lane];
    h2 = fmaxf(h2, 0.f);
    if (lane >= 14) h2 = 0.f;

    const float* w3 = W3 + t * 5 * 14 + min(lane, 4) * 14;
    float o = 0.f;
    #pragma unroll
    for (int k = 0; k < 14; k++)
        o = fmaf(w3[k], __shfl_sync(0xffffffffu, h2, k), o);
    if (lane < 5) out[b * 5 + lane] = o + b3[t * 5 + lane];
}

// ---------------- launch ----------------
extern "C" void kernel_launch(void* const* d_in, const int* in_sizes, int n_in,
                              void* d_out, int out_size)
{
    const float* x_s = (const float*)d_in[0];
    const float* x_p = (const float*)d_in[1];
    const int*   tt  = (const int*)d_in[2];
    const int*   dom = (const int*)d_in[3];
    const float* WsW = (const float*)d_in[4];
    const float* Wsb = (const float*)d_in[5];
    const float* WhW = (const float*)d_in[6];
    const float* Whb = (const float*)d_in[7];
    const float* WfW = (const float*)d_in[8];
    const float* Wfb = (const float*)d_in[9];
    const float* PcW = (const float*)d_in[10];
    const float* Pcb = (const float*)d_in[11];
    const float* PlW = (const float*)d_in[12];
    const float* Plb = (const float*)d_in[13];
    const float* H1W = (const float*)d_in[14];
    const float* H1b = (const float*)d_in[15];
    const float* H2W = (const float*)d_in[16];
    const float* H2b = (const float*)d_in[17];
    const float* H3W = (const float*)d_in[18];
    const float* H3b = (const float*)d_in[19];
    float* out = (float*)d_out;
    const int B = in_sizes[2];  // 1024

    float *s1, *s2, *s3, *p1, *x24, *U;
    cudaGetSymbolAddress((void**)&s1,  g_s1);
    cudaGetSymbolAddress((void**)&s2,  g_s2);
    cudaGetSymbolAddress((void**)&s3,  g_s3);
    cudaGetSymbolAddress((void**)&p1,  g_p1);
    cudaGetSymbolAddress((void**)&x24, g_x24);
    cudaGetSymbolAddress((void**)&U,   g_U);

    const size_t sm1 = (size_t)(3 * 66 * 68 + 36 * 3 * 9)   * sizeof(float); //  57.7 KB
    const size_t smp = (size_t)(3 * 66 * 68 + 12 * 3 * 9)   * sizeof(float); //  55.2 KB
    const size_t smw2 = (size_t)(36 * 6 * 36  + 16 * 36 * 32) * sizeof(float); // 104.8 KB
    const size_t smw3 = (size_t)(36 * 10 * 20 + 16 * 36 * 32) * sizeof(float); // 102.5 KB

    cudaFuncSetAttribute(convpool_kernel<3, 36, 64, false, false>,
                         cudaFuncAttributeMaxDynamicSharedMemorySize, (int)sm1);
    cudaFuncSetAttribute(convpool_kernel<3, 12, 64, true, true>,
                         cudaFuncAttributeMaxDynamicSharedMemorySize, (int)smp);
    cudaFuncSetAttribute(wino_conv_kernel<32, 2>,
                         cudaFuncAttributeMaxDynamicSharedMemorySize, (int)smw2);
    cudaFuncSetAttribute(wino_conv_kernel<16, 4>,
                         cudaFuncAttributeMaxDynamicSharedMemorySize, (int)smw3);

    // Winograd weight transform for hidden conv (once per launch; deterministic)
    wino_wt_kernel<<<(36 * 36 + 127) / 128, 128>>>(WhW, U);

    // shared branch
    convpool_kernel<3, 36, 64, false, false><<<B, 256, sm1>>>(x_s, WsW, Wsb, nullptr, s1);
    wino_conv_kernel<32, 2><<<dim3(8, B), 288, smw2>>>(s1, U, Whb, s2);
    wino_conv_kernel<16, 4><<<dim3(2, B), 288, smw3>>>(s2, U, Whb, s3);
    // private branch
    convpool_kernel<3, 12, 64, true, true><<<B, 256, smp>>>(x_p, PcW, Pcb, dom, p1);
    // FCs -> concat buffer
    fc12_kernel<2304,  true,  false><<<B / 8, 256>>>(s3, WfW, Wfb, nullptr, x24, 0);
    fc12_kernel<12288, false, true ><<<B / 8, 256>>>(p1, PlW, Plb, dom,     x24, 12);
    // routed heads -> output
    heads_kernel<<<B / 8, 256>>>(x24, tt, H1W, H1b, H2W, H2b, H3W, H3b, out);
}

// round 4
// speedup vs baseline: 1.3644x; 1.3644x over previous
#include <cuda_runtime.h>
#include <cstdint>

// ---------------- scratch (device globals; no allocation allowed) ----------------
__device__ float g_s1[1024 * 36 * 32 * 32];   // conv1 out (pooled)
__device__ float g_s2[1024 * 36 * 16 * 16];   // conv2 out (pooled)
__device__ float g_s3[1024 * 36 * 8 * 8];     // conv3 out (pooled)
__device__ float g_p1[1024 * 12 * 32 * 32];   // private conv out (pooled)
__device__ float g_x24[1024 * 24];            // concat [h | p]

// ---------------- fused conv3x3(SAME) + act + maxpool2 (R1 math, strip-occupancy) ----
// grid = (STRIPS, B). Block stages its row strip (+halo) in SMEM.
// Thread computes a 2x2 pooled tile = 4x4 conv pixels from a 6x6 patch (float4 LDS).
// WSMEM=false: weights via warp-uniform __ldg (oc uniform per warp) -> L1 broadcast.
template <int IC, int OC, int S, int STRIPS, bool WSMEM, bool LEAKY, bool USE_DOM, int NT>
__global__ void __launch_bounds__(NT)
convpool_kernel(const float* __restrict__ x,
                const float* __restrict__ Wbase,
                const float* __restrict__ Bbase,
                const int* __restrict__ dom_ptr,
                float* __restrict__ out)
{
    constexpr int RL  = S / STRIPS;   // conv rows per block
    constexpr int PH  = RL + 2;       // staged rows (halo)
    constexpr int P   = S + 4;        // padded stride (mult of 4 -> aligned float4)
    constexpr int HTY = RL / 4;
    constexpr int HTX = S / 4;
    constexpr int Sp  = S / 2;

    extern __shared__ float smem[];
    float* sx = smem;                       // IC * PH * P
    float* sw = smem + IC * PH * P;         // OC * IC * 9 (if WSMEM)

    const int strip = STRIPS == 1 ? 0 : blockIdx.x;
    const int b     = STRIPS == 1 ? blockIdx.x : blockIdx.y;
    const int tid   = threadIdx.x;

    int dom = 0;
    if (USE_DOM) dom = dom_ptr[0];
    const float* W  = Wbase + (size_t)dom * OC * IC * 9;
    const float* Bv = Bbase + (size_t)dom * OC;

    for (int i = tid; i < IC * PH * P; i += NT) sx[i] = 0.f;
    __syncthreads();

    const int r0   = strip * RL;
    const int gr0  = (r0 - 1 < 0) ? 0 : r0 - 1;
    const int gr1  = (r0 + RL + 1 > S) ? S : r0 + RL + 1;
    const int nrow = gr1 - gr0;
    const float* xb = x + (size_t)b * IC * S * S;
    for (int i = tid; i < IC * nrow * S; i += NT) {
        int c  = i / (nrow * S);
        int rr = (i / S) % nrow;
        int cc = i % S;
        int gr = gr0 + rr;
        sx[c * PH * P + (gr - r0 + 1) * P + (cc + 1)] = xb[c * S * S + gr * S + cc];
    }
    if (WSMEM)
        for (int i = tid; i < OC * IC * 9; i += NT) sw[i] = W[i];
    __syncthreads();

    constexpr int tilesPerOc = HTY * HTX;
    constexpr int tiles = OC * tilesPerOc;
    for (int t = tid; t < tiles; t += NT) {
        int oc  = t / tilesPerOc;
        int rem = t - oc * tilesPerOc;
        int ty  = rem / HTX;
        int tx  = rem - ty * HTX;

        float acc[16];
        #pragma unroll
        for (int i = 0; i < 16; i++) acc[i] = 0.f;

        const float* wp    = WSMEM ? (sw + oc * IC * 9) : (W + oc * IC * 9);
        const float* xbase = sx + (4 * ty) * P + 4 * tx;

        for (int ci = 0; ci < IC; ci++) {
            const float* xp = xbase + ci * PH * P;
            float w0, w1, w2, w3, w4, w5, w6, w7, w8;
            if (WSMEM) {
                w0 = wp[0]; w1 = wp[1]; w2 = wp[2];
                w3 = wp[3]; w4 = wp[4]; w5 = wp[5];
                w6 = wp[6]; w7 = wp[7]; w8 = wp[8];
            } else {            // warp-uniform -> L1 broadcast loads
                w0 = __ldg(wp + 0); w1 = __ldg(wp + 1); w2 = __ldg(wp + 2);
                w3 = __ldg(wp + 3); w4 = __ldg(wp + 4); w5 = __ldg(wp + 5);
                w6 = __ldg(wp + 6); w7 = __ldg(wp + 7); w8 = __ldg(wp + 8);
            }
            wp += 9;
            float p[6][6];
            #pragma unroll
            for (int r = 0; r < 6; r++) {
                float4 a  = *reinterpret_cast<const float4*>(xp + r * P);
                float4 bq = *reinterpret_cast<const float4*>(xp + r * P + 4);
                p[r][0] = a.x;  p[r][1] = a.y;  p[r][2] = a.z;  p[r][3] = a.w;
                p[r][4] = bq.x; p[r][5] = bq.y;
            }
            #pragma unroll
            for (int r = 0; r < 4; r++) {
                #pragma unroll
                for (int c = 0; c < 4; c++) {
                    float s = acc[r * 4 + c];
                    s = fmaf(w0, p[r][c],         s);
                    s = fmaf(w1, p[r][c + 1],     s);
                    s = fmaf(w2, p[r][c + 2],     s);
                    s = fmaf(w3, p[r + 1][c],     s);
                    s = fmaf(w4, p[r + 1][c + 1], s);
                    s = fmaf(w5, p[r + 1][c + 2], s);
                    s = fmaf(w6, p[r + 2][c],     s);
                    s = fmaf(w7, p[r + 2][c + 1], s);
                    s = fmaf(w8, p[r + 2][c + 2], s);
                    acc[r * 4 + c] = s;
                }
            }
        }
        // act(max(conv)+b) == pool(act(conv+b)) for monotonic act
        float bias = WSMEM ? Bv[oc] : __ldg(Bv + oc);
        int prow0 = strip * (RL / 2) + 2 * ty;
        float* ob = out + (((size_t)b * OC + oc) * Sp + prow0) * Sp + 2 * tx;
        #pragma unroll
        for (int pr = 0; pr < 2; pr++) {
            #pragma unroll
            for (int pc = 0; pc < 2; pc++) {
                float m = fmaxf(fmaxf(acc[(2*pr)*4 + 2*pc],   acc[(2*pr)*4 + 2*pc + 1]),
                                fmaxf(acc[(2*pr+1)*4 + 2*pc], acc[(2*pr+1)*4 + 2*pc + 1]));
                m += bias;
                float v;
                if (LEAKY) v = (m > 0.f) ? m : 0.001f * m;
                else       v = fmaxf(m, 0.f);
                ob[pr * Sp + pc] = v;
            }
        }
    }
}

// ---------------- FC: [B,K] @ W[12,K]^T + b -> concat buffer ----------------
template <int K, bool RELU, bool USE_DOM>
__global__ void fc12_kernel(const float* __restrict__ x,
                            const float* __restrict__ Wbase,
                            const float* __restrict__ Bbase,
                            const int* __restrict__ dom_ptr,
                            float* __restrict__ out, int out_off)
{
    const int warp = threadIdx.x >> 5;
    const int lane = threadIdx.x & 31;
    const int b = blockIdx.x * 8 + warp;
    int dom = 0;
    if (USE_DOM) dom = dom_ptr[0];
    const float* W = Wbase + (size_t)dom * 12 * K;
    const float4* xr = reinterpret_cast<const float4*>(x + (size_t)b * K);

    float4 acc[12];
    #pragma unroll
    for (int j = 0; j < 12; j++) acc[j] = make_float4(0.f, 0.f, 0.f, 0.f);

    for (int k4 = lane; k4 < K / 4; k4 += 32) {
        float4 xv = xr[k4];
        #pragma unroll
        for (int j = 0; j < 12; j++) {
            float4 wv = reinterpret_cast<const float4*>(W + (size_t)j * K)[k4];
            acc[j].x = fmaf(xv.x, wv.x, acc[j].x);
            acc[j].y = fmaf(xv.y, wv.y, acc[j].y);
            acc[j].z = fmaf(xv.z, wv.z, acc[j].z);
            acc[j].w = fmaf(xv.w, wv.w, acc[j].w);
        }
    }
    const float* Bv = Bbase + dom * 12;
    #pragma unroll
    for (int j = 0; j < 12; j++) {
        float s = (acc[j].x + acc[j].y) + (acc[j].z + acc[j].w);
        #pragma unroll
        for (int o = 16; o > 0; o >>= 1) s += __shfl_xor_sync(0xffffffffu, s, o);
        if (lane == j) {
            float v = s + Bv[j];
            if (RELU) v = fmaxf(v, 0.f);
            out[b * 24 + out_off + j] = v;
        }
    }
}

// ---------------- per-sample routed heads: 24 -> 28 -> 14 -> 5 ----------------
__global__ void heads_kernel(const float* __restrict__ x24,
                             const int* __restrict__ tt,
                             const float* __restrict__ W1, const float* __restrict__ b1,
                             const float* __restrict__ W2, const float* __restrict__ b2,
                             const float* __restrict__ W3, const float* __restrict__ b3,
                             float* __restrict__ out)
{
    const int warp = threadIdx.x >> 5;
    const int lane = threadIdx.x & 31;
    const int b = blockIdx.x * 8 + warp;
    const int t = tt[b];

    float xv = (lane < 24) ? x24[b * 24 + lane] : 0.f;

    const float* w1 = W1 + t * 28 * 24 + min(lane, 27) * 24;
    float h1 = 0.f;
    #pragma unroll
    for (int k = 0; k < 24; k++)
        h1 = fmaf(w1[k], __shfl_sync(0xffffffffu, xv, k), h1);
    if (lane < 28) h1 += b1[t * 28 + lane];
    h1 = fmaxf(h1, 0.f);
    if (lane >= 28) h1 = 0.f;

    const float* w2 = W2 + t * 14 * 28 + min(lane, 13) * 28;
    float h2 = 0.f;
    #pragma unroll
    for (int k = 0; k < 28; k++)
        h2 = fmaf(w2[k], __shfl_sync(0xffffffffu, h1, k), h2);
    if (lane < 14) h2 += b2[t * 14 + lane];
    h2 = fmaxf(h2, 0.f);
    if (lane >= 14) h2 = 0.f;

    const float* w3 = W3 + t * 5 * 14 + min(lane, 4) * 14;
    float o = 0.f;
    #pragma unroll
    for (int k = 0; k < 14; k++)
        o = fmaf(w3[k], __shfl_sync(0xffffffffu, h2, k), o);
    if (lane < 5) out[b * 5 + lane] = o + b3[t * 5 + lane];
}

// ---------------- launch ----------------
extern "C" void kernel_launch(void* const* d_in, const int* in_sizes, int n_in,
                              void* d_out, int out_size)
{
    const float* x_s = (const float*)d_in[0];
    const float* x_p = (const float*)d_in[1];
    const int*   tt  = (const int*)d_in[2];
    const int*   dom = (const int*)d_in[3];
    const float* WsW = (const float*)d_in[4];
    const float* Wsb = (const float*)d_in[5];
    const float* WhW = (const float*)d_in[6];
    const float* Whb = (const float*)d_in[7];
    const float* WfW = (const float*)d_in[8];
    const float* Wfb = (const float*)d_in[9];
    const float* PcW = (const float*)d_in[10];
    const float* Pcb = (const float*)d_in[11];
    const float* PlW = (const float*)d_in[12];
    const float* Plb = (const float*)d_in[13];
    const float* H1W = (const float*)d_in[14];
    const float* H1b = (const float*)d_in[15];
    const float* H2W = (const float*)d_in[16];
    const float* H2b = (const float*)d_in[17];
    const float* H3W = (const float*)d_in[18];
    const float* H3b = (const float*)d_in[19];
    float* out = (float*)d_out;
    const int B = in_sizes[2];  // 1024

    float *s1, *s2, *s3, *p1, *x24;
    cudaGetSymbolAddress((void**)&s1,  g_s1);
    cudaGetSymbolAddress((void**)&s2,  g_s2);
    cudaGetSymbolAddress((void**)&s3,  g_s3);
    cudaGetSymbolAddress((void**)&p1,  g_p1);
    cudaGetSymbolAddress((void**)&x24, g_x24);

    // conv1: whole image + weights in smem (3.9 KB weights)      -> 57.7 KB, 3 blk/SM
    const size_t sm1 = (size_t)(3 * 66 * 68 + 36 * 3 * 9)   * sizeof(float);
    // conv2: 4 row strips, weights via uniform LDG               -> 51.8 KB, 4 blk/SM
    const size_t sm2 = (size_t)(36 * 10 * 36)               * sizeof(float);
    // conv3: whole image, weights via uniform LDG                -> 51.8 KB, 4 blk/SM
    const size_t sm3 = (size_t)(36 * 18 * 20)               * sizeof(float);
    // private conv
    const size_t smp = (size_t)(3 * 66 * 68 + 12 * 3 * 9)   * sizeof(float);

    cudaFuncSetAttribute(convpool_kernel<3, 36, 64, 1, true,  false, false, 256>,
                         cudaFuncAttributeMaxDynamicSharedMemorySize, (int)sm1);
    cudaFuncSetAttribute(convpool_kernel<36, 36, 32, 4, false, false, false, 288>,
                         cudaFuncAttributeMaxDynamicSharedMemorySize, (int)sm2);
    cudaFuncSetAttribute(convpool_kernel<36, 36, 16, 1, false, false, false, 288>,
                         cudaFuncAttributeMaxDynamicSharedMemorySize, (int)sm3);
    cudaFuncSetAttribute(convpool_kernel<3, 12, 64, 1, true,  true,  true, 256>,
                         cudaFuncAttributeMaxDynamicSharedMemorySize, (int)smp);

    // shared branch
    convpool_kernel<3, 36, 64, 1, true, false, false, 256>
        <<<B, 256, sm1>>>(x_s, WsW, Wsb, nullptr, s1);
    convpool_kernel<36, 36, 32, 4, false, false, false, 288>
        <<<dim3(4, B), 288, sm2>>>(s1, WhW, Whb, nullptr, s2);
    convpool_kernel<36, 36, 16, 1, false, false, false, 288>
        <<<B, 288, sm3>>>(s2, WhW, Whb, nullptr, s3);
    // private branch
    convpool_kernel<3, 12, 64, 1, true, true, true, 256>
        <<<B, 256, smp>>>(x_p, PcW, Pcb, dom, p1);
    // FCs -> concat buffer
    fc12_kernel<2304,  true,  false><<<B / 8, 256>>>(s3, WfW, Wfb, nullptr, x24, 0);
    fc12_kernel<12288, false, true ><<<B / 8, 256>>>(p1, PlW, Plb, dom,     x24, 12);
    // routed heads -> output
    heads_kernel<<<B / 8, 256>>>(x24, tt, H1W, H1b, H2W, H2b, H3W, H3b, out);
}

// round 5
// speedup vs baseline: 1.3797x; 1.0112x over previous
#include <cuda_runtime.h>
#include <cstdint>

// ---------------- scratch (device globals; no allocation allowed) ----------------
__device__ float g_s1[1024 * 36 * 32 * 32];   // conv1 out (pooled)
__device__ float g_s2[1024 * 36 * 16 * 16];   // conv2 out (pooled)
__device__ float g_s3[1024 * 36 * 8 * 8];     // conv3 out (pooled)
__device__ float g_p1[1024 * 12 * 32 * 32];   // private conv out (pooled)
__device__ float g_x24[1024 * 24];            // concat [h | p]
__device__ float g_W2[9 * 40 * 40 * 2];       // hidden conv weights, tf32-split {hi,lo}, padded

// ---------------- tf32 helpers ----------------
__device__ __forceinline__ unsigned f2tf(float x) {
    unsigned r;
    asm("cvt.rna.tf32.f32 %0, %1;" : "=r"(r) : "f"(x));
    return r;
}
__device__ __forceinline__ void mma_tf32(float* d, const unsigned* a, const unsigned* b) {
    asm volatile(
        "mma.sync.aligned.m16n8k8.row.col.f32.tf32.tf32.f32 "
        "{%0,%1,%2,%3}, {%4,%5,%6,%7}, {%8,%9}, {%0,%1,%2,%3};"
        : "+f"(d[0]), "+f"(d[1]), "+f"(d[2]), "+f"(d[3])
        : "r"(a[0]), "r"(a[1]), "r"(a[2]), "r"(a[3]), "r"(b[0]), "r"(b[1]));
}

// ---------------- weight split precompute: WhW[oc36][ci36][3][3] -> g_W2[tap][ci40][oc40][2] ----
__global__ void wsplit_kernel(const float* __restrict__ W, float* __restrict__ W2)
{
    int idx = blockIdx.x * blockDim.x + threadIdx.x;
    if (idx >= 9 * 40 * 40) return;
    int tap = idx / 1600;
    int ci  = (idx / 40) % 40;
    int oc  = idx % 40;
    float hi = 0.f, lo = 0.f;
    if (ci < 36 && oc < 36) {
        float w = W[((size_t)oc * 36 + ci) * 9 + tap];
        hi = __uint_as_float(f2tf(w));
        float r = w - hi;
        lo = __uint_as_float(f2tf(r));
    }
    W2[idx * 2 + 0] = hi;
    W2[idx * 2 + 1] = lo;
}

// ---------------- tf32-split implicit-GEMM conv3x3 + relu + maxpool2 (hidden layers) ----
// grid = (STRIPS, B), 256 threads (8 warps). Strip = SR image rows.
// Warp owns a (2 rows x 16 cols) pixel block = 2 m16 tiles -> 2x2 pool fully in-warp.
// PH*P must be ≡ 8 (mod 32) for conflict-free A-fragment LDS.
template <int S, int STRIPS, int P>
__global__ void __launch_bounds__(256, 2)
tfconv_kernel(const float* __restrict__ x, const float* __restrict__ W2,
              const float* __restrict__ Bv, float* __restrict__ out)
{
    constexpr int SR  = S / STRIPS;     // rows per strip
    constexpr int PH  = SR + 2;
    constexpr int PHP = PH * P;
    static_assert(PHP % 32 == 8, "bank layout");
    constexpr int RPAIRS = SR / 2;
    constexpr int COLT   = S / 16;
    static_assert(RPAIRS * COLT == 8, "8 warps");
    constexpr int Sp = S / 2;

    extern __shared__ float sx[];       // 40 * PH * P

    const int strip = blockIdx.x;
    const int b     = blockIdx.y;
    const int tid   = threadIdx.x;
    const int w     = tid >> 5;
    const int lane  = tid & 31;

    // zero (incl. padded ci planes 36-39 and halos)
    for (int i = tid; i < 40 * PHP; i += 256) sx[i] = 0.f;
    __syncthreads();

    // stage strip rows [r0-1, r0+SR] clipped, with +1 col halo
    const int r0  = strip * SR;
    const int gr0 = (r0 - 1 < 0) ? 0 : r0 - 1;
    const int gr1 = (r0 + SR + 1 > S) ? S : r0 + SR + 1;
    const int nrow = gr1 - gr0;
    const float* xb = x + (size_t)b * 36 * S * S;
    for (int i = tid; i < 36 * nrow * S; i += 256) {
        int ci = i / (nrow * S);
        int rr = (i / S) % nrow;
        int c  = i % S;
        int gr = gr0 + rr;
        sx[ci * PHP + (gr - r0 + 1) * P + (c + 1)] = xb[ci * S * S + gr * S + c];
    }
    __syncthreads();

    // warp tile assignment
    const int rp   = w / COLT;               // row pair in strip
    const int c0   = (w % COLT) * 16;        // col base
    const int lr0  = 2 * rp;                 // local rows lr0, lr0+1
    const int la   = lane & 3;               // k-in-group
    const int lg   = lane >> 2;              // m-in-group

    float C[5][2][4];                        // [ntile][mtile][reg]
    #pragma unroll
    for (int n = 0; n < 5; n++)
        #pragma unroll
        for (int t = 0; t < 2; t++)
            #pragma unroll
            for (int j = 0; j < 4; j++) C[n][t][j] = 0.f;

    // per-lane invariant offsets
    const int aoff0 = la * PHP + lr0 * P + c0 + lg;       // tile0, a0
    const float2* W2v = reinterpret_cast<const float2*>(W2);

    for (int tap = 0; tap < 9; tap++) {
        const int dy = tap / 3, dx = tap % 3;
        const int abase = aoff0 + dy * P + dx;
        const int wbase = tap * 1600 + la * 40 + lg;       // element idx into [ci40][oc40]

        #pragma unroll
        for (int kt = 0; kt < 5; kt++) {
            // ---- A fragments (2 m-tiles), split hi/lo ----
            unsigned Ah[2][4], Al[2][4];
            #pragma unroll
            for (int t = 0; t < 2; t++) {
                const float* ap = sx + abase + t * P + kt * 8 * PHP;
                float x0 = ap[0];
                float x1 = ap[8];
                float x2 = ap[4 * PHP];
                float x3 = ap[4 * PHP + 8];
                Ah[t][0] = f2tf(x0); Al[t][0] = f2tf(x0 - __uint_as_float(Ah[t][0]));
                Ah[t][1] = f2tf(x1); Al[t][1] = f2tf(x1 - __uint_as_float(Ah[t][1]));
                Ah[t][2] = f2tf(x2); Al[t][2] = f2tf(x2 - __uint_as_float(Ah[t][2]));
                Ah[t][3] = f2tf(x3); Al[t][3] = f2tf(x3 - __uint_as_float(Ah[t][3]));
            }
            // ---- B fragments: LDG.64 {hi,lo} per reg ----
            unsigned Bh[5][2], Bl[5][2];
            #pragma unroll
            for (int n = 0; n < 5; n++) {
                float2 q0 = __ldg(W2v + wbase + kt * 8 * 40 + n * 8);
                float2 q1 = __ldg(W2v + wbase + kt * 8 * 40 + n * 8 + 4 * 40);
                Bh[n][0] = f2tf(q0.x); Bl[n][0] = f2tf(q0.y);
                Bh[n][1] = f2tf(q1.x); Bl[n][1] = f2tf(q1.y);
            }
            // ---- 3-term split MMAs ----
            #pragma unroll
            for (int n = 0; n < 5; n++)
                #pragma unroll
                for (int t = 0; t < 2; t++) {
                    mma_tf32(C[n][t], Ah[t], Bh[n]);
                    mma_tf32(C[n][t], Ah[t], Bl[n]);
                    mma_tf32(C[n][t], Al[t], Bh[n]);
                }
        }
    }

    // ---- fused 2x2 maxpool + bias + relu epilogue ----
    const int pr = strip * RPAIRS + rp;
    #pragma unroll
    for (int n = 0; n < 5; n++) {
        float m0 = fmaxf(C[n][0][0], C[n][1][0]);
        float m1 = fmaxf(C[n][0][1], C[n][1][1]);
        float m2 = fmaxf(C[n][0][2], C[n][1][2]);
        float m3 = fmaxf(C[n][0][3], C[n][1][3]);
        float p0 = fmaxf(m0, __shfl_xor_sync(0xffffffffu, m0, 4));
        float p1 = fmaxf(m1, __shfl_xor_sync(0xffffffffu, m1, 4));
        float p2 = fmaxf(m2, __shfl_xor_sync(0xffffffffu, m2, 4));
        float p3 = fmaxf(m3, __shfl_xor_sync(0xffffffffu, m3, 4));
        if ((lane & 4) == 0) {
            int oc0 = n * 8 + (lane & 3) * 2;
            if (oc0 < 36) {
                int pcb = c0 / 2 + ((lane >> 3) & 3);
                float b0 = __ldg(Bv + oc0);
                float b1 = __ldg(Bv + oc0 + 1);
                float* o0 = out + (((size_t)b * 36 + oc0) * Sp + pr) * Sp;
                float* o1 = o0 + (size_t)Sp * Sp;   // oc0+1
                o0[pcb]     = fmaxf(p0 + b0, 0.f);
                o1[pcb]     = fmaxf(p1 + b1, 0.f);
                o0[pcb + 4] = fmaxf(p2 + b0, 0.f);
                o1[pcb + 4] = fmaxf(p3 + b1, 0.f);
            }
        }
    }
}

// ---------------- direct conv3x3 + act + maxpool2 (R4, for 3-channel layers) ----------
template <int IC, int OC, int S, bool LEAKY, bool USE_DOM, int NT>
__global__ void __launch_bounds__(NT)
convpool_kernel(const float* __restrict__ x,
                const float* __restrict__ Wbase,
                const float* __restrict__ Bbase,
                const int* __restrict__ dom_ptr,
                float* __restrict__ out)
{
    constexpr int PH = S + 2;
    constexpr int P  = S + 4;
    constexpr int HT = S / 4;
    constexpr int Sp = S / 2;
    extern __shared__ float smem[];
    float* sx = smem;
    float* sw = smem + IC * PH * P;

    const int b   = blockIdx.x;
    const int tid = threadIdx.x;

    int dom = 0;
    if (USE_DOM) dom = dom_ptr[0];
    const float* W  = Wbase + (size_t)dom * OC * IC * 9;
    const float* Bv = Bbase + (size_t)dom * OC;

    for (int i = tid; i < IC * PH * P; i += NT) sx[i] = 0.f;
    __syncthreads();
    const float* xb = x + (size_t)b * IC * S * S;
    for (int i = tid; i < IC * S * S; i += NT) {
        int c  = i / (S * S);
        int r  = (i / S) % S;
        int cc = i % S;
        sx[c * PH * P + (r + 1) * P + (cc + 1)] = xb[i];
    }
    for (int i = tid; i < OC * IC * 9; i += NT) sw[i] = W[i];
    __syncthreads();

    constexpr int tilesPerOc = HT * HT;
    constexpr int tiles = OC * tilesPerOc;
    for (int t = tid; t < tiles; t += NT) {
        int oc  = t / tilesPerOc;
        int rem = t - oc * tilesPerOc;
        int ty  = rem / HT;
        int tx  = rem - ty * HT;

        float acc[16];
        #pragma unroll
        for (int i = 0; i < 16; i++) acc[i] = 0.f;

        const float* wp    = sw + oc * IC * 9;
        const float* xbase = sx + (4 * ty) * P + 4 * tx;

        for (int ci = 0; ci < IC; ci++) {
            const float* xp = xbase + ci * PH * P;
            float w0 = wp[0], w1 = wp[1], w2 = wp[2],
                  w3 = wp[3], w4 = wp[4], w5 = wp[5],
                  w6 = wp[6], w7 = wp[7], w8 = wp[8];
            wp += 9;
            float p[6][6];
            #pragma unroll
            for (int r = 0; r < 6; r++) {
                float4 a  = *reinterpret_cast<const float4*>(xp + r * P);
                float4 bq = *reinterpret_cast<const float4*>(xp + r * P + 4);
                p[r][0] = a.x;  p[r][1] = a.y;  p[r][2] = a.z;  p[r][3] = a.w;
                p[r][4] = bq.x; p[r][5] = bq.y;
            }
            #pragma unroll
            for (int r = 0; r < 4; r++) {
                #pragma unroll
                for (int c = 0; c < 4; c++) {
                    float s = acc[r * 4 + c];
                    s = fmaf(w0, p[r][c],         s);
                    s = fmaf(w1, p[r][c + 1],     s);
                    s = fmaf(w2, p[r][c + 2],     s);
                    s = fmaf(w3, p[r + 1][c],     s);
                    s = fmaf(w4, p[r + 1][c + 1], s);
                    s = fmaf(w5, p[r + 1][c + 2], s);
                    s = fmaf(w6, p[r + 2][c],     s);
                    s = fmaf(w7, p[r + 2][c + 1], s);
                    s = fmaf(w8, p[r + 2][c + 2], s);
                    acc[r * 4 + c] = s;
                }
            }
        }
        float bias = Bv[oc];
        float* ob = out + (((size_t)b * OC + oc) * Sp + 2 * ty) * Sp + 2 * tx;
        #pragma unroll
        for (int pr = 0; pr < 2; pr++) {
            #pragma unroll
            for (int pc = 0; pc < 2; pc++) {
                float m = fmaxf(fmaxf(acc[(2*pr)*4 + 2*pc],   acc[(2*pr)*4 + 2*pc + 1]),
                                fmaxf(acc[(2*pr+1)*4 + 2*pc], acc[(2*pr+1)*4 + 2*pc + 1]));
                m += bias;
                float v;
                if (LEAKY) v = (m > 0.f) ? m : 0.001f * m;
                else       v = fmaxf(m, 0.f);
                ob[pr * Sp + pc] = v;
            }
        }
    }
}

// ---------------- FC: [B,K] @ W[12,K]^T + b -> concat buffer ----------------
template <int K, bool RELU, bool USE_DOM>
__global__ void fc12_kernel(const float* __restrict__ x,
                            const float* __restrict__ Wbase,
                            const float* __restrict__ Bbase,
                            const int* __restrict__ dom_ptr,
                            float* __restrict__ out, int out_off)
{
    const int warp = threadIdx.x >> 5;
    const int lane = threadIdx.x & 31;
    const int b = blockIdx.x * 8 + warp;
    int dom = 0;
    if (USE_DOM) dom = dom_ptr[0];
    const float* W = Wbase + (size_t)dom * 12 * K;
    const float4* xr = reinterpret_cast<const float4*>(x + (size_t)b * K);

    float4 acc[12];
    #pragma unroll
    for (int j = 0; j < 12; j++) acc[j] = make_float4(0.f, 0.f, 0.f, 0.f);

    for (int k4 = lane; k4 < K / 4; k4 += 32) {
        float4 xv = xr[k4];
        #pragma unroll
        for (int j = 0; j < 12; j++) {
            float4 wv = reinterpret_cast<const float4*>(W + (size_t)j * K)[k4];
            acc[j].x = fmaf(xv.x, wv.x, acc[j].x);
            acc[j].y = fmaf(xv.y, wv.y, acc[j].y);
            acc[j].z = fmaf(xv.z, wv.z, acc[j].z);
            acc[j].w = fmaf(xv.w, wv.w, acc[j].w);
        }
    }
    const float* Bv = Bbase + dom * 12;
    #pragma unroll
    for (int j = 0; j < 12; j++) {
        float s = (acc[j].x + acc[j].y) + (acc[j].z + acc[j].w);
        #pragma unroll
        for (int o = 16; o > 0; o >>= 1) s += __shfl_xor_sync(0xffffffffu, s, o);
        if (lane == j) {
            float v = s + Bv[j];
            if (RELU) v = fmaxf(v, 0.f);
            out[b * 24 + out_off + j] = v;
        }
    }
}

// ---------------- per-sample routed heads: 24 -> 28 -> 14 -> 5 ----------------
__global__ void heads_kernel(const float* __restrict__ x24,
                             const int* __restrict__ tt,
                             const float* __restrict__ W1, const float* __restrict__ b1,
                             const float* __restrict__ W2, const float* __restrict__ b2,
                             const float* __restrict__ W3, const float* __restrict__ b3,
                             float* __restrict__ out)
{
    const int warp = threadIdx.x >> 5;
    const int lane = threadIdx.x & 31;
    const int b = blockIdx.x * 8 + warp;
    const int t = tt[b];

    float xv = (lane < 24) ? x24[b * 24 + lane] : 0.f;

    const float* w1 = W1 + t * 28 * 24 + min(lane, 27) * 24;
    float h1 = 0.f;
    #pragma unroll
    for (int k = 0; k < 24; k++)
        h1 = fmaf(w1[k], __shfl_sync(0xffffffffu, xv, k), h1);
    if (lane < 28) h1 += b1[t * 28 + lane];
    h1 = fmaxf(h1, 0.f);
    if (lane >= 28) h1 = 0.f;

    const float* w2 = W2 + t * 14 * 28 + min(lane, 13) * 28;
    float h2 = 0.f;
    #pragma unroll
    for (int k = 0; k < 28; k++)
        h2 = fmaf(w2[k], __shfl_sync(0xffffffffu, h1, k), h2);
    if (lane < 14) h2 += b2[t * 14 + lane];
    h2 = fmaxf(h2, 0.f);
    if (lane >= 14) h2 = 0.f;

    const float* w3 = W3 + t * 5 * 14 + min(lane, 4) * 14;
    float o = 0.f;
    #pragma unroll
    for (int k = 0; k < 14; k++)
        o = fmaf(w3[k], __shfl_sync(0xffffffffu, h2, k), o);
    if (lane < 5) out[b * 5 + lane] = o + b3[t * 5 + lane];
}

// ---------------- launch ----------------
extern "C" void kernel_launch(void* const* d_in, const int* in_sizes, int n_in,
                              void* d_out, int out_size)
{
    const float* x_s = (const float*)d_in[0];
    const float* x_p = (const float*)d_in[1];
    const int*   tt  = (const int*)d_in[2];
    const int*   dom = (const int*)d_in[3];
    const float* WsW = (const float*)d_in[4];
    const float* Wsb = (const float*)d_in[5];
    const float* WhW = (const float*)d_in[6];
    const float* Whb = (const float*)d_in[7];
    const float* WfW = (const float*)d_in[8];
    const float* Wfb = (const float*)d_in[9];
    const float* PcW = (const float*)d_in[10];
    const float* Pcb = (const float*)d_in[11];
    const float* PlW = (const float*)d_in[12];
    const float* Plb = (const float*)d_in[13];
    const float* H1W = (const float*)d_in[14];
    const float* H1b = (const float*)d_in[15];
    const float* H2W = (const float*)d_in[16];
    const float* H2b = (const float*)d_in[17];
    const float* H3W = (const float*)d_in[18];
    const float* H3b = (const float*)d_in[19];
    float* out = (float*)d_out;
    const int B = in_sizes[2];  // 1024

    float *s1, *s2, *s3, *p1, *x24, *W2;
    cudaGetSymbolAddress((void**)&s1,  g_s1);
    cudaGetSymbolAddress((void**)&s2,  g_s2);
    cudaGetSymbolAddress((void**)&s3,  g_s3);
    cudaGetSymbolAddress((void**)&p1,  g_p1);
    cudaGetSymbolAddress((void**)&x24, g_x24);
    cudaGetSymbolAddress((void**)&W2,  g_W2);

    const size_t sm1  = (size_t)(3 * 66 * 68 + 36 * 3 * 9) * sizeof(float);
    const size_t smp  = (size_t)(3 * 66 * 68 + 12 * 3 * 9) * sizeof(float);
    const size_t smt2 = (size_t)(40 * 10 * 36) * sizeof(float);   // 57.6 KB
    const size_t smt3 = (size_t)(40 * 18 * 20) * sizeof(float);   // 57.6 KB

    cudaFuncSetAttribute(convpool_kernel<3, 36, 64, false, false, 256>,
                         cudaFuncAttributeMaxDynamicSharedMemorySize, (int)sm1);
    cudaFuncSetAttribute(convpool_kernel<3, 12, 64, true, true, 256>,
                         cudaFuncAttributeMaxDynamicSharedMemorySize, (int)smp);
    cudaFuncSetAttribute(tfconv_kernel<32, 4, 36>,
                         cudaFuncAttributeMaxDynamicSharedMemorySize, (int)smt2);
    cudaFuncSetAttribute(tfconv_kernel<16, 1, 20>,
                         cudaFuncAttributeMaxDynamicSharedMemorySize, (int)smt3);

    // weight split (tiny; once per launch, deterministic)
    wsplit_kernel<<<(9 * 40 * 40 + 127) / 128, 128>>>(WhW, W2);

    // shared branch
    convpool_kernel<3, 36, 64, false, false, 256><<<B, 256, sm1>>>(x_s, WsW, Wsb, nullptr, s1);
    tfconv_kernel<32, 4, 36><<<dim3(4, B), 256, smt2>>>(s1, W2, Whb, s2);
    tfconv_kernel<16, 1, 20><<<dim3(1, B), 256, smt3>>>(s2, W2, Whb, s3);
    // private branch
    convpool_kernel<3, 12, 64, true, true, 256><<<B, 256, smp>>>(x_p, PcW, Pcb, dom, p1);
    // FCs -> concat buffer
    fc12_kernel<2304,  true,  false><<<B / 8, 256>>>(s3, WfW, Wfb, nullptr, x24, 0);
    fc12_kernel<12288, false, true ><<<B / 8, 256>>>(p1, PlW, Plb, dom,     x24, 12);
    // routed heads -> output
    heads_kernel<<<B / 8, 256>>>(x24, tt, H1W, H1b, H2W, H2b, H3W, H3b, out);
}

// round 6
// speedup vs baseline: 1.7843x; 1.2932x over previous
#include <cuda_runtime.h>
#include <cuda_bf16.h>
#include <cstdint>

// ---------------- scratch (device globals; no allocation allowed) ----------------
__device__ unsigned g_s1[1024 * 36 * 32 * 32]; // conv1 out, packed bf16x2(hi,lo)
__device__ unsigned g_s2[1024 * 36 * 16 * 16]; // conv2 out, packed bf16x2(hi,lo)
__device__ float    g_s3[1024 * 36 * 8 * 8];   // conv3 out (fp32, feeds FC)
__device__ float    g_p1[1024 * 12 * 32 * 32]; // private conv out
__device__ float    g_x24[1024 * 24];          // concat [h | p]
__device__ float    g_Wf[9 * 5 * 2 * 3 * 32 * 4]; // frag-ready split weights (138 KB)

// ---------------- packing helpers ----------------
__device__ __forceinline__ unsigned pack_hilo(float v) {
    __nv_bfloat16 h = __float2bfloat16_rn(v);
    float hf = __bfloat162float(h);
    __nv_bfloat16 l = __float2bfloat16_rn(v - hf);
    unsigned hu = (unsigned)__bfloat16_as_ushort(h);
    unsigned lu = (unsigned)__bfloat16_as_ushort(l);
    return (lu << 16) | hu;                 // low half = k-even = hi
}

__device__ __forceinline__ void mma_bf16(float* d, const unsigned* a, unsigned b0, unsigned b1) {
    asm volatile(
        "mma.sync.aligned.m16n8k16.row.col.f32.bf16.bf16.f32 "
        "{%0,%1,%2,%3}, {%4,%5,%6,%7}, {%8,%9}, {%0,%1,%2,%3};"
        : "+f"(d[0]), "+f"(d[1]), "+f"(d[2]), "+f"(d[3])
        : "r"(a[0]), "r"(a[1]), "r"(a[2]), "r"(a[3]), "r"(b0), "r"(b1));
}

// ---------------- weight prep: WhW[oc36][ci36][3][3] -> fragment-ready float4 ----------
// Layout: Wf[tap][kt(5)][ord(2)][q(3)][lane(32)] as float4 (each float = packed word).
// ord0 word = (hi,lo); ord1 = (lo,hi). Two MMAs with ord0+ord1 give all 4 split terms.
__global__ void wprep_kernel(const float* __restrict__ W, float* __restrict__ Wf)
{
    int idx = blockIdx.x * blockDim.x + threadIdx.x;
    if (idx >= 9 * 5 * 2 * 3 * 32) return;
    int lane = idx & 31;
    int q    = (idx >> 5) % 3;
    int ord  = (idx / 96) % 2;
    int kt   = (idx / 192) % 5;
    int tap  = idx / 960;
    int km = lane & 3, n = lane >> 2;
    int ci0 = kt * 8 + km, ci1 = ci0 + 4;
    int oc0 = q * 16 + n,  oc1 = oc0 + 8;

    auto pk = [&](int ci, int oc) -> float {
        float w = 0.f;
        if (ci < 36 && oc < 36) w = W[((size_t)oc * 36 + ci) * 9 + tap];
        __nv_bfloat16 h = __float2bfloat16_rn(w);
        float hf = __bfloat162float(h);
        __nv_bfloat16 l = __float2bfloat16_rn(w - hf);
        unsigned hu = (unsigned)__bfloat16_as_ushort(h);
        unsigned lu = (unsigned)__bfloat16_as_ushort(l);
        unsigned word = ord == 0 ? ((lu << 16) | hu) : ((hu << 16) | lu);
        return __uint_as_float(word);
    };
    float4 f;
    f.x = pk(ci0, oc0); f.y = pk(ci1, oc0);
    f.z = pk(ci0, oc1); f.w = pk(ci1, oc1);
    reinterpret_cast<float4*>(Wf)[idx] = f;
}

// ---------------- bf16-split implicit-GEMM conv3x3 + relu + maxpool2 ----------------
// grid = (STRIPS, B), 256 threads (8 warps). Warp: 2 pixel rows x 16 cols.
// A planes hold packed (hi,lo) words -> fragment regs loaded raw (no CVT).
// PH*P ≡ 8 (mod 32) -> conflict-free fragment LDS (validated layout).
template <int S, int STRIPS, int P, bool OUTPACK>
__global__ void __launch_bounds__(256, 2)
bfconv_kernel(const unsigned* __restrict__ x, const float* __restrict__ Wf,
              const float* __restrict__ Bv, void* __restrict__ outv)
{
    constexpr int SR  = S / STRIPS;
    constexpr int PH  = SR + 2;
    constexpr int PHP = PH * P;
    static_assert(PHP % 32 == 8, "bank layout");
    constexpr int RPAIRS = SR / 2;
    constexpr int COLT   = S / 16;
    static_assert(RPAIRS * COLT == 8, "8 warps");
    constexpr int Sp = S / 2;

    extern __shared__ unsigned sx[];    // 40 * PH * P packed words

    const int strip = blockIdx.x;
    const int b     = blockIdx.y;
    const int tid   = threadIdx.x;
    const int w     = tid >> 5;
    const int lane  = tid & 31;

    for (int i = tid; i < 40 * PHP; i += 256) sx[i] = 0u;
    __syncthreads();

    const int r0  = strip * SR;
    const int gr0 = (r0 - 1 < 0) ? 0 : r0 - 1;
    const int gr1 = (r0 + SR + 1 > S) ? S : r0 + SR + 1;
    const int nrow = gr1 - gr0;
    const unsigned* xb = x + (size_t)b * 36 * S * S;
    for (int i = tid; i < 36 * nrow * S; i += 256) {
        int ci = i / (nrow * S);
        int rr = (i / S) % nrow;
        int c  = i % S;
        int gr = gr0 + rr;
        sx[ci * PHP + (gr - r0 + 1) * P + (c + 1)] = xb[ci * S * S + gr * S + c];
    }
    __syncthreads();

    const int rp  = w / COLT;
    const int c0  = (w % COLT) * 16;
    const int lr0 = 2 * rp;
    const int la  = lane & 3;
    const int lg  = lane >> 2;

    float C[5][2][4];
    #pragma unroll
    for (int n = 0; n < 5; n++)
        #pragma unroll
        for (int t = 0; t < 2; t++)
            #pragma unroll
            for (int j = 0; j < 4; j++) C[n][t][j] = 0.f;

    const int aoff0 = la * PHP + lr0 * P + c0 + lg;
    const float4* Wf4 = reinterpret_cast<const float4*>(Wf);

    for (int tap = 0; tap < 9; tap++) {
        const int dy = tap / 3, dx = tap % 3;
        const int abase = aoff0 + dy * P + dx;
        const int wtap  = tap * (5 * 2 * 3 * 32);

        #pragma unroll
        for (int kt = 0; kt < 5; kt++) {
            // A fragments (raw packed words)
            unsigned A[2][4];
            #pragma unroll
            for (int t = 0; t < 2; t++) {
                const unsigned* ap = sx + abase + t * P + kt * 8 * PHP;
                A[t][0] = ap[0];
                A[t][1] = ap[8];
                A[t][2] = ap[4 * PHP];
                A[t][3] = ap[4 * PHP + 8];
            }
            // B fragments, both orderings, frag-ready float4 (LDG.128, L1/L2-hot)
            const int base = wtap + kt * (2 * 3 * 32);
            float4 q0a = __ldg(Wf4 + base + 0 * 32 + lane);
            float4 q1a = __ldg(Wf4 + base + 1 * 32 + lane);
            float4 q2a = __ldg(Wf4 + base + 2 * 32 + lane);
            float4 q0b = __ldg(Wf4 + base + 3 * 32 + lane);
            float4 q1b = __ldg(Wf4 + base + 4 * 32 + lane);
            float4 q2b = __ldg(Wf4 + base + 5 * 32 + lane);

            unsigned Ba[5][2] = {
                {__float_as_uint(q0a.x), __float_as_uint(q0a.y)},
                {__float_as_uint(q0a.z), __float_as_uint(q0a.w)},
                {__float_as_uint(q1a.x), __float_as_uint(q1a.y)},
                {__float_as_uint(q1a.z), __float_as_uint(q1a.w)},
                {__float_as_uint(q2a.x), __float_as_uint(q2a.y)} };
            unsigned Bb[5][2] = {
                {__float_as_uint(q0b.x), __float_as_uint(q0b.y)},
                {__float_as_uint(q0b.z), __float_as_uint(q0b.w)},
                {__float_as_uint(q1b.x), __float_as_uint(q1b.y)},
                {__float_as_uint(q1b.z), __float_as_uint(q1b.w)},
                {__float_as_uint(q2b.x), __float_as_uint(q2b.y)} };

            #pragma unroll
            for (int n = 0; n < 5; n++)
                #pragma unroll
                for (int t = 0; t < 2; t++) {
                    mma_bf16(C[n][t], A[t], Ba[n][0], Ba[n][1]);   // ahbh + albl
                    mma_bf16(C[n][t], A[t], Bb[n][0], Bb[n][1]);   // ahbl + albh
                }
        }
    }

    // ---- fused 2x2 maxpool + bias + relu epilogue (validated mapping) ----
    const int pr = strip * RPAIRS + rp;
    #pragma unroll
    for (int n = 0; n < 5; n++) {
        float m0 = fmaxf(C[n][0][0], C[n][1][0]);
        float m1 = fmaxf(C[n][0][1], C[n][1][1]);
        float m2 = fmaxf(C[n][0][2], C[n][1][2]);
        float m3 = fmaxf(C[n][0][3], C[n][1][3]);
        float p0 = fmaxf(m0, __shfl_xor_sync(0xffffffffu, m0, 4));
        float p1 = fmaxf(m1, __shfl_xor_sync(0xffffffffu, m1, 4));
        float p2 = fmaxf(m2, __shfl_xor_sync(0xffffffffu, m2, 4));
        float p3 = fmaxf(m3, __shfl_xor_sync(0xffffffffu, m3, 4));
        if ((lane & 4) == 0) {
            int oc0 = n * 8 + (lane & 3) * 2;
            if (oc0 < 36) {
                int pcb = c0 / 2 + ((lane >> 3) & 3);
                float b0 = __ldg(Bv + oc0);
                float b1 = __ldg(Bv + oc0 + 1);
                float v00 = fmaxf(p0 + b0, 0.f);
                float v01 = fmaxf(p1 + b1, 0.f);
                float v10 = fmaxf(p2 + b0, 0.f);
                float v11 = fmaxf(p3 + b1, 0.f);
                size_t o0 = (((size_t)b * 36 + oc0) * Sp + pr) * Sp;
                size_t o1 = o0 + (size_t)Sp * Sp;
                if (OUTPACK) {
                    unsigned* out = (unsigned*)outv;
                    out[o0 + pcb]     = pack_hilo(v00);
                    out[o1 + pcb]     = pack_hilo(v01);
                    out[o0 + pcb + 4] = pack_hilo(v10);
                    out[o1 + pcb + 4] = pack_hilo(v11);
                } else {
                    float* out = (float*)outv;
                    out[o0 + pcb]     = v00;
                    out[o1 + pcb]     = v01;
                    out[o0 + pcb + 4] = v10;
                    out[o1 + pcb + 4] = v11;
                }
            }
        }
    }
}

// ---------------- direct conv3x3 + act + maxpool2 (3-channel layers) ----------------
template <int IC, int OC, int S, bool LEAKY, bool USE_DOM, bool OUTPACK, int NT>
__global__ void __launch_bounds__(NT)
convpool_kernel(const float* __restrict__ x,
                const float* __restrict__ Wbase,
                const float* __restrict__ Bbase,
                const int* __restrict__ dom_ptr,
                void* __restrict__ outv)
{
    constexpr int PH = S + 2;
    constexpr int P  = S + 4;
    constexpr int HT = S / 4;
    constexpr int Sp = S / 2;
    extern __shared__ float smem[];
    float* sx = smem;
    float* sw = smem + IC * PH * P;

    const int b   = blockIdx.x;
    const int tid = threadIdx.x;

    int dom = 0;
    if (USE_DOM) dom = dom_ptr[0];
    const float* W  = Wbase + (size_t)dom * OC * IC * 9;
    const float* Bv = Bbase + (size_t)dom * OC;

    for (int i = tid; i < IC * PH * P; i += NT) sx[i] = 0.f;
    __syncthreads();
    const float* xb = x + (size_t)b * IC * S * S;
    for (int i = tid; i < IC * S * S; i += NT) {
        int c  = i / (S * S);
        int r  = (i / S) % S;
        int cc = i % S;
        sx[c * PH * P + (r + 1) * P + (cc + 1)] = xb[i];
    }
    for (int i = tid; i < OC * IC * 9; i += NT) sw[i] = W[i];
    __syncthreads();

    constexpr int tilesPerOc = HT * HT;
    constexpr int tiles = OC * tilesPerOc;
    for (int t = tid; t < tiles; t += NT) {
        int oc  = t / tilesPerOc;
        int rem = t - oc * tilesPerOc;
        int ty  = rem / HT;
        int tx  = rem - ty * HT;

        float acc[16];
        #pragma unroll
        for (int i = 0; i < 16; i++) acc[i] = 0.f;

        const float* wp    = sw + oc * IC * 9;
        const float* xbase = sx + (4 * ty) * P + 4 * tx;

        for (int ci = 0; ci < IC; ci++) {
            const float* xp = xbase + ci * PH * P;
            float w0 = wp[0], w1 = wp[1], w2 = wp[2],
                  w3 = wp[3], w4 = wp[4], w5 = wp[5],
                  w6 = wp[6], w7 = wp[7], w8 = wp[8];
            wp += 9;
            float p[6][6];
            #pragma unroll
            for (int r = 0; r < 6; r++) {
                float4 a  = *reinterpret_cast<const float4*>(xp + r * P);
                float4 bq = *reinterpret_cast<const float4*>(xp + r * P + 4);
                p[r][0] = a.x;  p[r][1] = a.y;  p[r][2] = a.z;  p[r][3] = a.w;
                p[r][4] = bq.x; p[r][5] = bq.y;
            }
            #pragma unroll
            for (int r = 0; r < 4; r++) {
                #pragma unroll
                for (int c = 0; c < 4; c++) {
                    float s = acc[r * 4 + c];
                    s = fmaf(w0, p[r][c],         s);
                    s = fmaf(w1, p[r][c + 1],     s);
                    s = fmaf(w2, p[r][c + 2],     s);
                    s = fmaf(w3, p[r + 1][c],     s);
                    s = fmaf(w4, p[r + 1][c + 1], s);
                    s = fmaf(w5, p[r + 1][c + 2], s);
                    s = fmaf(w6, p[r + 2][c],     s);
                    s = fmaf(w7, p[r + 2][c + 1], s);
                    s = fmaf(w8, p[r + 2][c + 2], s);
                    acc[r * 4 + c] = s;
                }
            }
        }
        float bias = Bv[oc];
        size_t ob = (((size_t)b * OC + oc) * Sp + 2 * ty) * Sp + 2 * tx;
        #pragma unroll
        for (int pr = 0; pr < 2; pr++) {
            #pragma unroll
            for (int pc = 0; pc < 2; pc++) {
                float m = fmaxf(fmaxf(acc[(2*pr)*4 + 2*pc],   acc[(2*pr)*4 + 2*pc + 1]),
                                fmaxf(acc[(2*pr+1)*4 + 2*pc], acc[(2*pr+1)*4 + 2*pc + 1]));
                m += bias;
                float v;
                if (LEAKY) v = (m > 0.f) ? m : 0.001f * m;
                else       v = fmaxf(m, 0.f);
                if (OUTPACK) ((unsigned*)outv)[ob + pr * Sp + pc] = pack_hilo(v);
                else         ((float*)outv)[ob + pr * Sp + pc] = v;
            }
        }
    }
}

// ---------------- FC: [B,K] @ W[12,K]^T + b -> concat buffer ----------------
template <int K, bool RELU, bool USE_DOM>
__global__ void fc12_kernel(const float* __restrict__ x,
                            const float* __restrict__ Wbase,
                            const float* __restrict__ Bbase,
                            const int* __restrict__ dom_ptr,
                            float* __restrict__ out, int out_off)
{
    const int warp = threadIdx.x >> 5;
    const int lane = threadIdx.x & 31;
    const int b = blockIdx.x * 8 + warp;
    int dom = 0;
    if (USE_DOM) dom = dom_ptr[0];
    const float* W = Wbase + (size_t)dom * 12 * K;
    const float4* xr = reinterpret_cast<const float4*>(x + (size_t)b * K);

    float4 acc[12];
    #pragma unroll
    for (int j = 0; j < 12; j++) acc[j] = make_float4(0.f, 0.f, 0.f, 0.f);

    for (int k4 = lane; k4 < K / 4; k4 += 32) {
        float4 xv = xr[k4];
        #pragma unroll
        for (int j = 0; j < 12; j++) {
            float4 wv = reinterpret_cast<const float4*>(W + (size_t)j * K)[k4];
            acc[j].x = fmaf(xv.x, wv.x, acc[j].x);
            acc[j].y = fmaf(xv.y, wv.y, acc[j].y);
            acc[j].z = fmaf(xv.z, wv.z, acc[j].z);
            acc[j].w = fmaf(xv.w, wv.w, acc[j].w);
        }
    }
    const float* Bv = Bbase + dom * 12;
    #pragma unroll
    for (int j = 0; j < 12; j++) {
        float s = (acc[j].x + acc[j].y) + (acc[j].z + acc[j].w);
        #pragma unroll
        for (int o = 16; o > 0; o >>= 1) s += __shfl_xor_sync(0xffffffffu, s, o);
        if (lane == j) {
            float v = s + Bv[j];
            if (RELU) v = fmaxf(v, 0.f);
            out[b * 24 + out_off + j] = v;
        }
    }
}

// ---------------- per-sample routed heads: 24 -> 28 -> 14 -> 5 ----------------
__global__ void heads_kernel(const float* __restrict__ x24,
                             const int* __restrict__ tt,
                             const float* __restrict__ W1, const float* __restrict__ b1,
                             const float* __restrict__ W2, const float* __restrict__ b2,
                             const float* __restrict__ W3, const float* __restrict__ b3,
                             float* __restrict__ out)
{
    const int warp = threadIdx.x >> 5;
    const int lane = threadIdx.x & 31;
    const int b = blockIdx.x * 8 + warp;
    const int t = tt[b];

    float xv = (lane < 24) ? x24[b * 24 + lane] : 0.f;

    const float* w1 = W1 + t * 28 * 24 + min(lane, 27) * 24;
    float h1 = 0.f;
    #pragma unroll
    for (int k = 0; k < 24; k++)
        h1 = fmaf(w1[k], __shfl_sync(0xffffffffu, xv, k), h1);
    if (lane < 28) h1 += b1[t * 28 + lane];
    h1 = fmaxf(h1, 0.f);
    if (lane >= 28) h1 = 0.f;

    const float* w2 = W2 + t * 14 * 28 + min(lane, 13) * 28;
    float h2 = 0.f;
    #pragma unroll
    for (int k = 0; k < 28; k++)
        h2 = fmaf(w2[k], __shfl_sync(0xffffffffu, h1, k), h2);
    if (lane < 14) h2 += b2[t * 14 + lane];
    h2 = fmaxf(h2, 0.f);
    if (lane >= 14) h2 = 0.f;

    const float* w3 = W3 + t * 5 * 14 + min(lane, 4) * 14;
    float o = 0.f;
    #pragma unroll
    for (int k = 0; k < 14; k++)
        o = fmaf(w3[k], __shfl_sync(0xffffffffu, h2, k), o);
    if (lane < 5) out[b * 5 + lane] = o + b3[t * 5 + lane];
}

// ---------------- launch ----------------
extern "C" void kernel_launch(void* const* d_in, const int* in_sizes, int n_in,
                              void* d_out, int out_size)
{
    const float* x_s = (const float*)d_in[0];
    const float* x_p = (const float*)d_in[1];
    const int*   tt  = (const int*)d_in[2];
    const int*   dom = (const int*)d_in[3];
    const float* WsW = (const float*)d_in[4];
    const float* Wsb = (const float*)d_in[5];
    const float* WhW = (const float*)d_in[6];
    const float* Whb = (const float*)d_in[7];
    const float* WfW = (const float*)d_in[8];
    const float* Wfb = (const float*)d_in[9];
    const float* PcW = (const float*)d_in[10];
    const float* Pcb = (const float*)d_in[11];
    const float* PlW = (const float*)d_in[12];
    const float* Plb = (const float*)d_in[13];
    const float* H1W = (const float*)d_in[14];
    const float* H1b = (const float*)d_in[15];
    const float* H2W = (const float*)d_in[16];
    const float* H2b = (const float*)d_in[17];
    const float* H3W = (const float*)d_in[18];
    const float* H3b = (const float*)d_in[19];
    float* out = (float*)d_out;
    const int B = in_sizes[2];  // 1024

    unsigned *s1, *s2;
    float *s3, *p1, *x24, *Wf;
    cudaGetSymbolAddress((void**)&s1,  g_s1);
    cudaGetSymbolAddress((void**)&s2,  g_s2);
    cudaGetSymbolAddress((void**)&s3,  g_s3);
    cudaGetSymbolAddress((void**)&p1,  g_p1);
    cudaGetSymbolAddress((void**)&x24, g_x24);
    cudaGetSymbolAddress((void**)&Wf,  g_Wf);

    const size_t sm1  = (size_t)(3 * 66 * 68 + 36 * 3 * 9) * sizeof(float);
    const size_t smp  = (size_t)(3 * 66 * 68 + 12 * 3 * 9) * sizeof(float);
    const size_t smb2 = (size_t)(40 * 10 * 36) * sizeof(unsigned);   // 57.6 KB
    const size_t smb3 = (size_t)(40 * 18 * 20) * sizeof(unsigned);   // 57.6 KB

    cudaFuncSetAttribute(convpool_kernel<3, 36, 64, false, false, true, 256>,
                         cudaFuncAttributeMaxDynamicSharedMemorySize, (int)sm1);
    cudaFuncSetAttribute(convpool_kernel<3, 12, 64, true, true, false, 256>,
                         cudaFuncAttributeMaxDynamicSharedMemorySize, (int)smp);
    cudaFuncSetAttribute(bfconv_kernel<32, 4, 36, true>,
                         cudaFuncAttributeMaxDynamicSharedMemorySize, (int)smb2);
    cudaFuncSetAttribute(bfconv_kernel<16, 1, 20, false>,
                         cudaFuncAttributeMaxDynamicSharedMemorySize, (int)smb3);

    // fragment-ready split weights (tiny; every launch, deterministic)
    wprep_kernel<<<(9 * 5 * 2 * 3 * 32 + 127) / 128, 128>>>(WhW, Wf);

    // shared branch
    convpool_kernel<3, 36, 64, false, false, true, 256>
        <<<B, 256, sm1>>>(x_s, WsW, Wsb, nullptr, s1);
    bfconv_kernel<32, 4, 36, true ><<<dim3(4, B), 256, smb2>>>(s1, Wf, Whb, s2);
    bfconv_kernel<16, 1, 20, false><<<dim3(1, B), 256, smb3>>>(s2, Wf, Whb, s3);
    // private branch
    convpool_kernel<3, 12, 64, true, true, false, 256>
        <<<B, 256, smp>>>(x_p, PcW, Pcb, dom, p1);
    // FCs -> concat buffer
    fc12_kernel<2304,  true,  false><<<B / 8, 256>>>(s3, WfW, Wfb, nullptr, x24, 0);
    fc12_kernel<12288, false, true ><<<B / 8, 256>>>(p1, PlW, Plb, dom,     x24, 12);
    // routed heads -> output
    heads_kernel<<<B / 8, 256>>>(x24, tt, H1W, H1b, H2W, H2b, H3W, H3b, out);
}